// round 12
// baseline (speedup 1.0000x reference)
#include <cuda_runtime.h>
#include <cuda_bf16.h>
#include <climits>
#include <stdint.h>

// ---------------- problem constants ----------------
#define NSEC 9
#define T_   30
#define H_   41
#define WD_  2048
#define FM_  50
#define KH_  6
#define KW_  40
#define WP_  502
#define THRESHF 23.0f
#define DELTA  0.004f
#define POOLED_ELEMS (NSEC*T_*FM_*WP_)   // 6,777,000

// ---------------- tiling ----------------
#define NT   7            // N tiles of 8 fm (56, fm 50..55 zero)
#define NC   15           // K chunks of 16 (K = 240 exact)
#define WIN_BLK 64        // pool windows per block (256 ow)
#define CSTAGE 304        // staged x cols per row (256 + 39 halo + pad)
#define XPITCH 152        // u32 words per row per phase array
#define XROWU32 (9*XPITCH)        // 1368 u32 per (split,phase) array
#define BFRAG_SEC (NC*3*NT*64)    // u32 per section = 20160 (80,640 B)
#define CAPFIX 32768

// smem layout (bytes)
#define SM_XB   0                          // 6 * 9 * 152 u32 = 32,832 B
#define SM_B    32832                      // 80,640 B
#define SM_POOL 113472                     // 50 * 65 f32 = 13,000 B
#define SM_KEY  126472
#define SM_TOTAL 126592

__device__ int g_key[NSEC];
__device__ int g_nfix;
__device__ int g_fixlist[CAPFIX];
__device__ __align__(16) unsigned g_bfrag[NSEC*BFRAG_SEC];

// ---------------- helpers ----------------
__device__ __forceinline__ void split3(float v, unsigned short& u1,
                                       unsigned short& u2, unsigned short& u3) {
    __nv_bfloat16 h1 = __float2bfloat16(v);
    float r1 = v - __bfloat162float(h1);
    __nv_bfloat16 h2 = __float2bfloat16(r1);
    float r2 = r1 - __bfloat162float(h2);
    __nv_bfloat16 h3 = __float2bfloat16(r2);
    u1 = __bfloat16_as_ushort(h1);
    u2 = __bfloat16_as_ushort(h2);
    u3 = __bfloat16_as_ushort(h3);
}

__device__ __forceinline__ void mma16816(float* d, const unsigned* a,
                                         const unsigned* b) {
    asm volatile(
        "mma.sync.aligned.m16n8k16.row.col.f32.bf16.bf16.f32 "
        "{%0,%1,%2,%3}, {%4,%5,%6,%7}, {%8,%9}, {%0,%1,%2,%3};"
        : "+f"(d[0]), "+f"(d[1]), "+f"(d[2]), "+f"(d[3])
        : "r"(a[0]), "r"(a[1]), "r"(a[2]), "r"(a[3]), "r"(b[0]), "r"(b[1]));
}

// ---------------- kernels ----------------
__global__ void init_keys_kernel() {
    if (threadIdx.x < NSEC) g_key[threadIdx.x] = INT_MAX;
    if (threadIdx.x == 0) g_nfix = 0;
}

// Pre-split weights into per-lane mma B-fragment layout:
// g_bfrag[((sec*NC + c)*3 + s)*NT + nt][lane][2]  (u32 pairs b0,b1)
__global__ void prep_bfrag_kernel(const float* __restrict__ W) {
    int sec = blockIdx.x;
    for (int idx = threadIdx.x; idx < NC*NT*32; idx += 256) {
        int c  = idx / (NT*32);
        int r  = idx - c*(NT*32);
        int nt = r >> 5;
        int l  = r & 31;
        int q = l & 3, g = l >> 2;
        int n = nt*8 + g;
        int k0 = 16*c + 2*q;
        unsigned short u[4][3];
#pragma unroll
        for (int e = 0; e < 4; ++e) {
            int k = k0 + (e >> 1)*8 + (e & 1);
            float wv = (n < FM_) ? W[sec*(FM_*KH_*KW_) + n*240 + k] : 0.0f;
            split3(wv, u[e][0], u[e][1], u[e][2]);
        }
#pragma unroll
        for (int s = 0; s < 3; ++s) {
            int base = (((sec*NC + c)*3 + s)*NT + nt)*64 + l*2;
            g_bfrag[base]     = (unsigned)u[0][s] | ((unsigned)u[1][s] << 16);
            g_bfrag[base + 1] = (unsigned)u[2][s] | ((unsigned)u[3][s] << 16);
        }
    }
}

__global__ __launch_bounds__(256, 1)
void conv_mma_kernel(const float* __restrict__ x, float* __restrict__ out) {
    extern __shared__ unsigned char sm[];
    unsigned* xs = (unsigned*)(sm + SM_XB);
    unsigned* sb = (unsigned*)(sm + SM_B);
    float*  pool = (float*)(sm + SM_POOL);
    int*    skey = (int*)(sm + SM_KEY);

    const int tid = threadIdx.x, wid = tid >> 5, lane = tid & 31;
    const int bx  = blockIdx.x;
    const int sec = bx / (T_*8);
    const int rem = bx - sec*(T_*8);
    const int t   = rem >> 3;
    const int chk = rem & 7;
    const int col0 = chk << 8;           // 256 ow per block
    const int wgbase = chk << 6;         // 64 windows per block

    if (tid == 0) *skey = INT_MAX;

    // ---- stage B fragments (prebuilt, per-lane layout) ----
    {
        const float4* src = (const float4*)(g_bfrag + sec*BFRAG_SEC);
        float4* dst = (float4*)sb;
        for (int i = tid; i < BFRAG_SEC/4; i += 256) dst[i] = src[i];
    }
    // ---- stage x: 3 bf16 splits x 2 phases (aligned u32-pair arrays) ----
    {
        unsigned short* xh = (unsigned short*)xs;
        const float* xg = x + (t*H_ + 4*sec) * WD_;
        for (int i = tid; i < 9*CSTAGE; i += 256) {
            int r = i / CSTAGE;
            int cl = i - r*CSTAGE;
            int gc = col0 + cl;
            float v = (gc < WD_) ? xg[r*WD_ + gc] : 0.0f;
            unsigned short u[3];
            split3(v, u[0], u[1], u[2]);
#pragma unroll
            for (int s = 0; s < 3; ++s) {
                xh[((s*2 + 0)*9 + r)*2*XPITCH + cl] = u[s];         // phase 0
                if (cl)
                    xh[((s*2 + 1)*9 + r)*2*XPITCH + cl - 1] = u[s]; // phase 1
            }
        }
    }
    __syncthreads();

    const int q = lane & 3, g = lane >> 2;
    const int oh = g >> 2, ow_in = g & 3;
    const int phase = ow_in & 1;
    const unsigned* xph[3];
#pragma unroll
    for (int s = 0; s < 3; ++s) xph[s] = xs + (s*2 + phase)*XROWU32;
    const unsigned long long* sb64 = (const unsigned long long*)sb;

    constexpr int SAi[6] = {0, 0, 1, 0, 1, 2};
    constexpr int SBi[6] = {0, 1, 0, 2, 1, 0};

#pragma unroll 1
    for (int pass = 0; pass < 4; ++pass) {
        const int wl0 = wid*8 + pass*2;
        float d[2][NT][4];
#pragma unroll
        for (int w2 = 0; w2 < 2; ++w2)
#pragma unroll
            for (int nt = 0; nt < NT; ++nt)
#pragma unroll
                for (int j = 0; j < 4; ++j) d[w2][nt][j] = 0.0f;

        int wordb[2];
#pragma unroll
        for (int w2 = 0; w2 < 2; ++w2)
            wordb[w2] = ((wl0 + w2)*4 + ow_in + 2*q) >> 1;

#pragma unroll 1
        for (int c = 0; c < NC; ++c) {
            int kh0 = (2*c) / 5;
            int wo0 = 8*c - 20*kh0;
            int kh8 = (2*c + 1) / 5;
            int wo8 = 8*c + 4 - 20*kh8;

            unsigned long long bb[3][NT];
#pragma unroll
            for (int s = 0; s < 3; ++s)
#pragma unroll
                for (int nt = 0; nt < NT; ++nt)
                    bb[s][nt] = sb64[((c*3 + s)*NT + nt)*32 + lane];

#pragma unroll
            for (int w2 = 0; w2 < 2; ++w2) {
                int o0 = (oh + kh0)*XPITCH + wordb[w2] + wo0;
                int o8 = (oh + kh8)*XPITCH + wordb[w2] + wo8;
                unsigned a[3][4];
#pragma unroll
                for (int s = 0; s < 3; ++s) {
                    a[s][0] = xph[s][o0];
                    a[s][1] = xph[s][o0 + 2*XPITCH];
                    a[s][2] = xph[s][o8];
                    a[s][3] = xph[s][o8 + 2*XPITCH];
                }
#pragma unroll
                for (int p = 0; p < 6; ++p)
#pragma unroll
                    for (int nt = 0; nt < NT; ++nt)
                        mma16816(d[w2][nt], a[SAi[p]],
                                 (const unsigned*)&bb[SBi[p]][nt]);
            }
        }

        // ---- epilogue: dual-threshold + 4x4 pool via ballots ----
#pragma unroll
        for (int w2 = 0; w2 < 2; ++w2) {
            unsigned long long mdef = 0ull, mband = 0ull;
#pragma unroll
            for (int nt = 0; nt < NT; ++nt) {
                unsigned bd[4], bm[4];
#pragma unroll
                for (int j = 0; j < 4; ++j) {
                    bd[j] = __ballot_sync(0xffffffffu,
                                          d[w2][nt][j] > THRESHF + DELTA);
                    bm[j] = __ballot_sync(0xffffffffu,
                                          d[w2][nt][j] > THRESHF - DELTA);
                }
                unsigned ed = bd[0] | bd[2], od = bd[1] | bd[3];
                unsigned eb = bm[0] | bm[2], ob = bm[1] | bm[3];
#pragma unroll
                for (int u = 0; u < 4; ++u) {
                    unsigned sel = 0x11111111u << u;
                    if (ed & sel) mdef  |= 1ull << (nt*8 + 2*u);
                    if (od & sel) mdef  |= 1ull << (nt*8 + 2*u + 1);
                    if (eb & sel) mband |= 1ull << (nt*8 + 2*u);
                    if (ob & sel) mband |= 1ull << (nt*8 + 2*u + 1);
                }
            }
            int wloc = wl0 + w2;
            int wg = wgbase + wloc;
            if (wg < WP_) {
                pool[lane*65 + wloc] = ((mdef >> lane) & 1ull) ? 1.0f : 0.0f;
                if (lane < FM_ - 32)
                    pool[(lane + 32)*65 + wloc] =
                        ((mdef >> (lane + 32)) & 1ull) ? 1.0f : 0.0f;
                if (lane == 0) {
                    if (mdef)
                        atomicMin(skey,
                            (int)((__ffsll((long long)mdef) - 1)*WP_ + wg));
                    unsigned long long need = mband & ~mdef;
                    if (need) {
                        int nfm = __popcll(need);
                        int base = atomicAdd(&g_nfix, nfm);
                        unsigned long long m = need;
                        while (m) {
                            int fm = __ffsll((long long)m) - 1;
                            m &= m - 1;
                            if (base < CAPFIX)
                                g_fixlist[base] =
                                    (((sec*T_ + t)*64 + fm) << 9) | wg;
                            ++base;
                        }
                    }
                }
            }
        }
    }
    __syncthreads();

    // ---- coalesced pooled store + winner key ----
    for (int i = tid; i < FM_*WIN_BLK; i += 256) {
        int fm = i >> 6, w = i & 63;
        if (wgbase + w < WP_)
            out[((sec*T_ + t)*FM_ + fm)*WP_ + wgbase + w] = pool[fm*65 + w];
    }
    if (tid == 0 && *skey != INT_MAX)
        atomicMin(&g_key[sec], (t << 15) | *skey);
}

// Exact recompute of band windows in the reference-matching fp32 chain order
// (kh outer ascending, kw inner ascending, single fmaf chain per cell) —
// identical to the R6 kernel whose output matched the reference bit-exactly.
__global__ void fixup_kernel(const float* __restrict__ x,
                             const float* __restrict__ W,
                             float* __restrict__ out) {
    int n = g_nfix;
    if (n > CAPFIX) n = CAPFIX;
    int lane = threadIdx.x & 31;
    int warp = (blockIdx.x*blockDim.x + threadIdx.x) >> 5;
    int nwarp = (gridDim.x*blockDim.x) >> 5;
    for (int e = warp; e < n; e += nwarp) {
        int rec = g_fixlist[e];
        int wg = rec & 511;
        int sf = rec >> 9;
        int fm = sf & 63;
        int st = sf >> 6;
        int sec = st / T_, t = st - sec*T_;
        bool fire = false;
        if (lane < 16) {
            int oh = lane >> 2;
            int ow = wg*4 + (lane & 3);
            const float* xg = x + (t*H_ + 4*sec)*WD_;
            const float* wv = W + (sec*FM_ + fm)*240;
            float acc = 0.0f;
#pragma unroll 1
            for (int kh = 0; kh < KH_; ++kh) {
                const float* xr = xg + (oh + kh)*WD_ + ow;
                const float* wr = wv + kh*KW_;
#pragma unroll 1
                for (int kw = 0; kw < KW_; ++kw)
                    acc = fmaf(xr[kw], wr[kw], acc);
            }
            fire = acc > THRESHF;
        }
        unsigned bal = __ballot_sync(0xffffffffu, fire);
        if (bal && lane == 0) {
            out[((sec*T_ + t)*FM_ + fm)*WP_ + wg] = 1.0f;
            atomicMin(&g_key[sec], (t << 15) | (fm*WP_ + wg));
        }
    }
}

__global__ void finalize_kernel(float* __restrict__ out, long long out_size) {
    int s = threadIdx.x;
    if (s < NSEC && out_size >= (long long)(POOLED_ELEMS + NSEC)) {
        int k = g_key[s];
        out[POOLED_ELEMS + s] = (k == INT_MAX) ? -1.0f
                                               : (float)((k & 32767) / WP_);
    }
}

extern "C" void kernel_launch(void* const* d_in, const int* in_sizes, int n_in,
                              void* d_out, int out_size) {
    const float* x = (const float*)d_in[0];
    const float* W = (const float*)d_in[1];
    if (n_in >= 2 && in_sizes[0] == NSEC*FM_*KH_*KW_) {
        const float* tmp = x; x = W; W = tmp;
    }
    float* out = (float*)d_out;

    cudaFuncSetAttribute(conv_mma_kernel,
                         cudaFuncAttributeMaxDynamicSharedMemorySize, SM_TOTAL);

    init_keys_kernel<<<1, 32>>>();
    prep_bfrag_kernel<<<NSEC, 256>>>(W);
    conv_mma_kernel<<<NSEC*T_*8, 256, SM_TOTAL>>>(x, out);
    fixup_kernel<<<96, 128>>>(x, W, out);
    finalize_kernel<<<1, 32>>>(out, (long long)out_size);
}

// round 13
// speedup vs baseline: 3.1170x; 3.1170x over previous
#include <cuda_runtime.h>
#include <cuda_bf16.h>
#include <climits>
#include <stdint.h>

// ---------------- problem constants ----------------
#define NSEC 9
#define T_   30
#define H_   41
#define WD_  2048
#define FM_  50
#define KH_  6
#define KW_  40
#define WP_  502
#define THRESHF 23.0f
#define DELTA  0.004f
#define POOLED_ELEMS (NSEC*T_*FM_*WP_)   // 6,777,000

// ---------------- tiling ----------------
#define NT   7            // N tiles of 8 fm (56, fm 50..55 zero)
#define NC   15           // K chunks of 16 (K = 240 exact)
#define NSPL 2            // bf16 splits (guard-band absorbs dropped terms)
#define NPROD 3           // b1w1, b1w2, b2w1
#define WIN_BLK 64        // pool windows per block (256 ow)
#define CSTAGE 304        // staged x cols per row (256 + 39 halo + pad)
#define XPITCH 152        // u32 words per row per phase array
#define XROWU32 (9*XPITCH)            // 1368 u32 per (split,phase) array
#define BFRAG_SEC (NC*NSPL*NT*64)     // u32 per section = 13440 (53,760 B)
#define CAPFIX 32768

// smem layout (bytes)
#define SM_XB   0                          // 4 * 1368 u32 = 21,888 B
#define SM_B    21888                      // 53,760 B
#define SM_POOL 75648                      // 50 * 65 f32 = 13,000 B
#define SM_KEY  88648
#define SM_TOTAL 88768

__device__ int g_key[NSEC];
__device__ int g_nfix;
__device__ int g_fixlist[CAPFIX];
__device__ __align__(16) unsigned g_bfrag[NSEC*BFRAG_SEC];

// ---------------- helpers ----------------
__device__ __forceinline__ void split2(float v, unsigned short& u1,
                                       unsigned short& u2) {
    __nv_bfloat16 h1 = __float2bfloat16(v);
    float r1 = v - __bfloat162float(h1);
    __nv_bfloat16 h2 = __float2bfloat16(r1);
    u1 = __bfloat16_as_ushort(h1);
    u2 = __bfloat16_as_ushort(h2);
}

__device__ __forceinline__ void mma16816(float* d, const unsigned* a,
                                         const unsigned* b) {
    asm volatile(
        "mma.sync.aligned.m16n8k16.row.col.f32.bf16.bf16.f32 "
        "{%0,%1,%2,%3}, {%4,%5,%6,%7}, {%8,%9}, {%0,%1,%2,%3};"
        : "+f"(d[0]), "+f"(d[1]), "+f"(d[2]), "+f"(d[3])
        : "r"(a[0]), "r"(a[1]), "r"(a[2]), "r"(a[3]), "r"(b[0]), "r"(b[1]));
}

// ---------------- kernels ----------------
__global__ void init_keys_kernel() {
    if (threadIdx.x < NSEC) g_key[threadIdx.x] = INT_MAX;
    if (threadIdx.x == 0) g_nfix = 0;
}

// Pre-split weights into per-lane mma B-fragment layout:
// g_bfrag[((sec*NC + c)*NSPL + s)*NT + nt][lane][2]  (u32 pairs b0,b1)
__global__ void prep_bfrag_kernel(const float* __restrict__ W) {
    int sec = blockIdx.x;
    for (int idx = threadIdx.x; idx < NC*NT*32; idx += 256) {
        int c  = idx / (NT*32);
        int r  = idx - c*(NT*32);
        int nt = r >> 5;
        int l  = r & 31;
        int q = l & 3, g = l >> 2;
        int n = nt*8 + g;
        int k0 = 16*c + 2*q;
        unsigned short u[4][NSPL];
#pragma unroll
        for (int e = 0; e < 4; ++e) {
            int k = k0 + (e >> 1)*8 + (e & 1);
            float wv = (n < FM_) ? W[sec*(FM_*KH_*KW_) + n*240 + k] : 0.0f;
            split2(wv, u[e][0], u[e][1]);
        }
#pragma unroll
        for (int s = 0; s < NSPL; ++s) {
            int base = (((sec*NC + c)*NSPL + s)*NT + nt)*64 + l*2;
            g_bfrag[base]     = (unsigned)u[0][s] | ((unsigned)u[1][s] << 16);
            g_bfrag[base + 1] = (unsigned)u[2][s] | ((unsigned)u[3][s] << 16);
        }
    }
}

__global__ __launch_bounds__(256, 2)
void conv_mma_kernel(const float* __restrict__ x, float* __restrict__ out) {
    extern __shared__ unsigned char sm[];
    unsigned* xs = (unsigned*)(sm + SM_XB);
    unsigned* sb = (unsigned*)(sm + SM_B);
    float*  pool = (float*)(sm + SM_POOL);
    int*    skey = (int*)(sm + SM_KEY);

    const int tid = threadIdx.x, wid = tid >> 5, lane = tid & 31;
    const int bx  = blockIdx.x;
    const int sec = bx / (T_*8);
    const int rem = bx - sec*(T_*8);
    const int t   = rem >> 3;
    const int chk = rem & 7;
    const int col0 = chk << 8;           // 256 ow per block
    const int wgbase = chk << 6;         // 64 windows per block

    if (tid == 0) *skey = INT_MAX;

    // ---- stage B fragments (prebuilt, per-lane layout) ----
    {
        const float4* src = (const float4*)(g_bfrag + sec*BFRAG_SEC);
        float4* dst = (float4*)sb;
        for (int i = tid; i < BFRAG_SEC/4; i += 256) dst[i] = src[i];
    }
    // ---- stage x: 2 bf16 splits x 2 phases (aligned u32-pair arrays) ----
    {
        unsigned short* xh = (unsigned short*)xs;
        const float* xg = x + (t*H_ + 4*sec) * WD_;
        for (int i = tid; i < 9*CSTAGE; i += 256) {
            int r = i / CSTAGE;
            int cl = i - r*CSTAGE;
            int gc = col0 + cl;
            float v = (gc < WD_) ? xg[r*WD_ + gc] : 0.0f;
            unsigned short u[NSPL];
            split2(v, u[0], u[1]);
#pragma unroll
            for (int s = 0; s < NSPL; ++s) {
                xh[((s*2 + 0)*9 + r)*2*XPITCH + cl] = u[s];         // phase 0
                if (cl)
                    xh[((s*2 + 1)*9 + r)*2*XPITCH + cl - 1] = u[s]; // phase 1
            }
        }
    }
    __syncthreads();

    const int q = lane & 3, g = lane >> 2;
    const int oh = g >> 2, ow_in = g & 3;
    const int phase = ow_in & 1;
    const unsigned* xph[NSPL];
#pragma unroll
    for (int s = 0; s < NSPL; ++s) xph[s] = xs + (s*2 + phase)*XROWU32;
    const unsigned long long* sb64 = (const unsigned long long*)sb;

    constexpr int SAi[NPROD] = {0, 0, 1};
    constexpr int SBi[NPROD] = {0, 1, 0};

#pragma unroll 1
    for (int pass = 0; pass < 4; ++pass) {
        const int wl0 = wid*8 + pass*2;
        float d[2][NT][4];
#pragma unroll
        for (int w2 = 0; w2 < 2; ++w2)
#pragma unroll
            for (int nt = 0; nt < NT; ++nt)
#pragma unroll
                for (int j = 0; j < 4; ++j) d[w2][nt][j] = 0.0f;

        int wordb[2];
#pragma unroll
        for (int w2 = 0; w2 < 2; ++w2)
            wordb[w2] = ((wl0 + w2)*4 + ow_in + 2*q) >> 1;

#pragma unroll 1
        for (int c = 0; c < NC; ++c) {
            int kh0 = (2*c) / 5;
            int wo0 = 8*c - 20*kh0;
            int kh8 = (2*c + 1) / 5;
            int wo8 = 8*c + 4 - 20*kh8;

            unsigned long long bb[NSPL][NT];
#pragma unroll
            for (int s = 0; s < NSPL; ++s)
#pragma unroll
                for (int nt = 0; nt < NT; ++nt)
                    bb[s][nt] = sb64[((c*NSPL + s)*NT + nt)*32 + lane];

#pragma unroll
            for (int w2 = 0; w2 < 2; ++w2) {
                int o0 = (oh + kh0)*XPITCH + wordb[w2] + wo0;
                int o8 = (oh + kh8)*XPITCH + wordb[w2] + wo8;
                unsigned a[NSPL][4];
#pragma unroll
                for (int s = 0; s < NSPL; ++s) {
                    a[s][0] = xph[s][o0];
                    a[s][1] = xph[s][o0 + 2*XPITCH];
                    a[s][2] = xph[s][o8];
                    a[s][3] = xph[s][o8 + 2*XPITCH];
                }
#pragma unroll
                for (int p = 0; p < NPROD; ++p)
#pragma unroll
                    for (int nt = 0; nt < NT; ++nt)
                        mma16816(d[w2][nt], a[SAi[p]],
                                 (const unsigned*)&bb[SBi[p]][nt]);
            }
        }

        // ---- epilogue: dual-threshold + 4x4 pool via ballots ----
#pragma unroll
        for (int w2 = 0; w2 < 2; ++w2) {
            unsigned long long mdef = 0ull, mband = 0ull;
#pragma unroll
            for (int nt = 0; nt < NT; ++nt) {
                unsigned bd[4], bm[4];
#pragma unroll
                for (int j = 0; j < 4; ++j) {
                    bd[j] = __ballot_sync(0xffffffffu,
                                          d[w2][nt][j] > THRESHF + DELTA);
                    bm[j] = __ballot_sync(0xffffffffu,
                                          d[w2][nt][j] > THRESHF - DELTA);
                }
                unsigned ed = bd[0] | bd[2], od = bd[1] | bd[3];
                unsigned eb = bm[0] | bm[2], ob = bm[1] | bm[3];
#pragma unroll
                for (int u = 0; u < 4; ++u) {
                    unsigned sel = 0x11111111u << u;
                    if (ed & sel) mdef  |= 1ull << (nt*8 + 2*u);
                    if (od & sel) mdef  |= 1ull << (nt*8 + 2*u + 1);
                    if (eb & sel) mband |= 1ull << (nt*8 + 2*u);
                    if (ob & sel) mband |= 1ull << (nt*8 + 2*u + 1);
                }
            }
            int wloc = wl0 + w2;
            int wg = wgbase + wloc;
            if (wg < WP_) {
                pool[lane*65 + wloc] = ((mdef >> lane) & 1ull) ? 1.0f : 0.0f;
                if (lane < FM_ - 32)
                    pool[(lane + 32)*65 + wloc] =
                        ((mdef >> (lane + 32)) & 1ull) ? 1.0f : 0.0f;
                if (lane == 0) {
                    if (mdef)
                        atomicMin(skey,
                            (int)((__ffsll((long long)mdef) - 1)*WP_ + wg));
                    unsigned long long need = mband & ~mdef;
                    if (need) {
                        int nfm = __popcll(need);
                        int base = atomicAdd(&g_nfix, nfm);
                        unsigned long long m = need;
                        while (m) {
                            int fm = __ffsll((long long)m) - 1;
                            m &= m - 1;
                            if (base < CAPFIX)
                                g_fixlist[base] =
                                    (((sec*T_ + t)*64 + fm) << 9) | wg;
                            ++base;
                        }
                    }
                }
            }
        }
    }
    __syncthreads();

    // ---- coalesced pooled store + winner key ----
    for (int i = tid; i < FM_*WIN_BLK; i += 256) {
        int fm = i >> 6, w = i & 63;
        if (wgbase + w < WP_)
            out[((sec*T_ + t)*FM_ + fm)*WP_ + wgbase + w] = pool[fm*65 + w];
    }
    if (tid == 0 && *skey != INT_MAX)
        atomicMin(&g_key[sec], (t << 15) | *skey);
}

// Exact recompute of band windows in the reference-matching fp32 chain order
// (kh outer ascending, kw inner ascending, single fmaf chain per cell).
__global__ void fixup_kernel(const float* __restrict__ x,
                             const float* __restrict__ W,
                             float* __restrict__ out) {
    int n = g_nfix;
    if (n > CAPFIX) n = CAPFIX;
    int lane = threadIdx.x & 31;
    int warp = (blockIdx.x*blockDim.x + threadIdx.x) >> 5;
    int nwarp = (gridDim.x*blockDim.x) >> 5;
    for (int e = warp; e < n; e += nwarp) {
        int rec = g_fixlist[e];
        int wg = rec & 511;
        int sf = rec >> 9;
        int fm = sf & 63;
        int st = sf >> 6;
        int sec = st / T_, t = st - sec*T_;
        bool fire = false;
        if (lane < 16) {
            int oh = lane >> 2;
            int ow = wg*4 + (lane & 3);
            const float* xg = x + (t*H_ + 4*sec)*WD_;
            const float* wv = W + (sec*FM_ + fm)*240;
            float acc = 0.0f;
#pragma unroll 1
            for (int kh = 0; kh < KH_; ++kh) {
                const float* xr = xg + (oh + kh)*WD_ + ow;
                const float* wr = wv + kh*KW_;
#pragma unroll 1
                for (int kw = 0; kw < KW_; ++kw)
                    acc = fmaf(xr[kw], wr[kw], acc);
            }
            fire = acc > THRESHF;
        }
        unsigned bal = __ballot_sync(0xffffffffu, fire);
        if (bal && lane == 0) {
            out[((sec*T_ + t)*FM_ + fm)*WP_ + wg] = 1.0f;
            atomicMin(&g_key[sec], (t << 15) | (fm*WP_ + wg));
        }
    }
}

__global__ void finalize_kernel(float* __restrict__ out, long long out_size) {
    int s = threadIdx.x;
    if (s < NSEC && out_size >= (long long)(POOLED_ELEMS + NSEC)) {
        int k = g_key[s];
        out[POOLED_ELEMS + s] = (k == INT_MAX) ? -1.0f
                                               : (float)((k & 32767) / WP_);
    }
}

extern "C" void kernel_launch(void* const* d_in, const int* in_sizes, int n_in,
                              void* d_out, int out_size) {
    const float* x = (const float*)d_in[0];
    const float* W = (const float*)d_in[1];
    if (n_in >= 2 && in_sizes[0] == NSEC*FM_*KH_*KW_) {
        const float* tmp = x; x = W; W = tmp;
    }
    float* out = (float*)d_out;

    cudaFuncSetAttribute(conv_mma_kernel,
                         cudaFuncAttributeMaxDynamicSharedMemorySize, SM_TOTAL);

    init_keys_kernel<<<1, 32>>>();
    prep_bfrag_kernel<<<NSEC, 256>>>(W);
    conv_mma_kernel<<<NSEC*T_*8, 256, SM_TOTAL>>>(x, out);
    fixup_kernel<<<96, 128>>>(x, W, out);
    finalize_kernel<<<1, 32>>>(out, (long long)out_size);
}

// round 14
// speedup vs baseline: 3.6661x; 1.1761x over previous
#include <cuda_runtime.h>
#include <cuda_bf16.h>
#include <climits>
#include <stdint.h>

// ---------------- problem constants ----------------
#define NSEC 9
#define T_   30
#define H_   41
#define WD_  2048
#define FM_  50
#define KH_  6
#define KW_  40
#define WP_  502
#define THRESHF 23.0f
#define DELTA  0.30f
#define POOLED_ELEMS (NSEC*T_*FM_*WP_)   // 6,777,000

// ---------------- tiling ----------------
#define NT   7            // N tiles of 8 fm (56, fm 50..55 zero)
#define NC   15           // K chunks of 16 (K = 240 exact)
#define WIN_BLK 64        // pool windows per block (256 ow)
#define CSTAGE 304        // staged x cols per row (256 + 39 halo + pad)
#define XPITCH 152        // u32 words per row per phase array
#define XROWU32 (9*XPITCH)        // 1368 u32 per phase array
#define BFRAG_SEC (NC*NT*64)      // u32 per section = 6720 (26,880 B)
#define CAPFIX 262144

// smem layout (bytes)
#define SM_XB   0                          // 2 * 1368 u32 = 10,944 B
#define SM_B    10944                      // 26,880 B
#define SM_POOL 37824                      // 50 * 65 f32 = 13,000 B
#define SM_KEY  50824
#define SM_TOTAL 50944

__device__ int g_key[NSEC];
__device__ int g_nfix;
__device__ int g_fixlist[CAPFIX];
__device__ __align__(16) unsigned g_bfrag[NSEC*BFRAG_SEC];

// ---------------- helpers ----------------
__device__ __forceinline__ void mma16816(float* d, const unsigned* a,
                                         const unsigned* b) {
    asm volatile(
        "mma.sync.aligned.m16n8k16.row.col.f32.bf16.bf16.f32 "
        "{%0,%1,%2,%3}, {%4,%5,%6,%7}, {%8,%9}, {%0,%1,%2,%3};"
        : "+f"(d[0]), "+f"(d[1]), "+f"(d[2]), "+f"(d[3])
        : "r"(a[0]), "r"(a[1]), "r"(a[2]), "r"(a[3]), "r"(b[0]), "r"(b[1]));
}

// ---------------- kernels ----------------
__global__ void init_keys_kernel() {
    if (threadIdx.x < NSEC) g_key[threadIdx.x] = INT_MAX;
    if (threadIdx.x == 0) g_nfix = 0;
}

// Pre-convert weights (bf16) into per-lane mma B-fragment layout:
// g_bfrag[((sec*NC + c)*NT + nt)*64 + lane*2 + {0,1}]
__global__ void prep_bfrag_kernel(const float* __restrict__ W) {
    int sec = blockIdx.x;
    for (int idx = threadIdx.x; idx < NC*NT*32; idx += 256) {
        int c  = idx / (NT*32);
        int r  = idx - c*(NT*32);
        int nt = r >> 5;
        int l  = r & 31;
        int q = l & 3, g = l >> 2;
        int n = nt*8 + g;
        int k0 = 16*c + 2*q;
        unsigned short u[4];
#pragma unroll
        for (int e = 0; e < 4; ++e) {
            int k = k0 + (e >> 1)*8 + (e & 1);
            float wv = (n < FM_) ? W[sec*(FM_*KH_*KW_) + n*240 + k] : 0.0f;
            u[e] = __bfloat16_as_ushort(__float2bfloat16(wv));
        }
        int base = ((sec*NC + c)*NT + nt)*64 + l*2;
        g_bfrag[base]     = (unsigned)u[0] | ((unsigned)u[1] << 16);
        g_bfrag[base + 1] = (unsigned)u[2] | ((unsigned)u[3] << 16);
    }
}

__global__ __launch_bounds__(256, 2)
void conv_mma_kernel(const float* __restrict__ x, float* __restrict__ out) {
    extern __shared__ unsigned char sm[];
    unsigned* xs = (unsigned*)(sm + SM_XB);
    unsigned* sb = (unsigned*)(sm + SM_B);
    float*  pool = (float*)(sm + SM_POOL);
    int*    skey = (int*)(sm + SM_KEY);

    const int tid = threadIdx.x, wid = tid >> 5, lane = tid & 31;
    const int bx  = blockIdx.x;
    const int sec = bx / (T_*8);
    const int rem = bx - sec*(T_*8);
    const int t   = rem >> 3;
    const int chk = rem & 7;
    const int col0 = chk << 8;           // 256 ow per block
    const int wgbase = chk << 6;         // 64 windows per block

    if (tid == 0) *skey = INT_MAX;

    // ---- stage B fragments (prebuilt, per-lane layout) ----
    {
        const float4* src = (const float4*)(g_bfrag + sec*BFRAG_SEC);
        float4* dst = (float4*)sb;
        for (int i = tid; i < BFRAG_SEC/4; i += 256) dst[i] = src[i];
    }
    // ---- stage x: bf16, 2 phases (aligned u32-pair arrays) ----
    {
        unsigned short* xh = (unsigned short*)xs;
        const float* xg = x + (t*H_ + 4*sec) * WD_;
        for (int i = tid; i < 9*CSTAGE; i += 256) {
            int r = i / CSTAGE;
            int cl = i - r*CSTAGE;
            int gc = col0 + cl;
            float v = (gc < WD_) ? xg[r*WD_ + gc] : 0.0f;
            unsigned short u = __bfloat16_as_ushort(__float2bfloat16(v));
            xh[r*2*XPITCH + cl] = u;                          // phase 0
            if (cl) xh[(9 + r)*2*XPITCH + cl - 1] = u;        // phase 1
        }
    }
    __syncthreads();

    const int q = lane & 3, g = lane >> 2;
    const int oh = g >> 2, ow_in = g & 3;
    const int phase = ow_in & 1;
    const unsigned* xp = xs + phase*XROWU32;
    const unsigned long long* sb64 = (const unsigned long long*)sb;

#pragma unroll 1
    for (int pass = 0; pass < 4; ++pass) {
        const int wl0 = wid*8 + pass*2;
        float d[2][NT][4];
#pragma unroll
        for (int w2 = 0; w2 < 2; ++w2)
#pragma unroll
            for (int nt = 0; nt < NT; ++nt)
#pragma unroll
                for (int j = 0; j < 4; ++j) d[w2][nt][j] = 0.0f;

        int wordb[2];
#pragma unroll
        for (int w2 = 0; w2 < 2; ++w2)
            wordb[w2] = ((wl0 + w2)*4 + ow_in + 2*q) >> 1;

#pragma unroll 1
        for (int c = 0; c < NC; ++c) {
            int kh0 = (2*c) / 5;
            int wo0 = 8*c - 20*kh0;
            int kh8 = (2*c + 1) / 5;
            int wo8 = 8*c + 4 - 20*kh8;

            unsigned long long bb[NT];
#pragma unroll
            for (int nt = 0; nt < NT; ++nt)
                bb[nt] = sb64[((c)*NT + nt)*32 + lane];

#pragma unroll
            for (int w2 = 0; w2 < 2; ++w2) {
                int o0 = (oh + kh0)*XPITCH + wordb[w2] + wo0;
                int o8 = (oh + kh8)*XPITCH + wordb[w2] + wo8;
                unsigned a[4];
                a[0] = xp[o0];
                a[1] = xp[o0 + 2*XPITCH];
                a[2] = xp[o8];
                a[3] = xp[o8 + 2*XPITCH];
#pragma unroll
                for (int nt = 0; nt < NT; ++nt)
                    mma16816(d[w2][nt], a, (const unsigned*)&bb[nt]);
            }
        }

        // ---- epilogue: dual-threshold + 4x4 pool via ballots ----
#pragma unroll
        for (int w2 = 0; w2 < 2; ++w2) {
            unsigned long long mdef = 0ull, mband = 0ull;
#pragma unroll
            for (int nt = 0; nt < NT; ++nt) {
                unsigned bd[4], bm[4];
#pragma unroll
                for (int j = 0; j < 4; ++j) {
                    bd[j] = __ballot_sync(0xffffffffu,
                                          d[w2][nt][j] > THRESHF + DELTA);
                    bm[j] = __ballot_sync(0xffffffffu,
                                          d[w2][nt][j] > THRESHF - DELTA);
                }
                unsigned ed = bd[0] | bd[2], od = bd[1] | bd[3];
                unsigned eb = bm[0] | bm[2], ob = bm[1] | bm[3];
#pragma unroll
                for (int u = 0; u < 4; ++u) {
                    unsigned sel = 0x11111111u << u;
                    if (ed & sel) mdef  |= 1ull << (nt*8 + 2*u);
                    if (od & sel) mdef  |= 1ull << (nt*8 + 2*u + 1);
                    if (eb & sel) mband |= 1ull << (nt*8 + 2*u);
                    if (ob & sel) mband |= 1ull << (nt*8 + 2*u + 1);
                }
            }
            int wloc = wl0 + w2;
            int wg = wgbase + wloc;
            if (wg < WP_) {
                pool[lane*65 + wloc] = ((mdef >> lane) & 1ull) ? 1.0f : 0.0f;
                if (lane < FM_ - 32)
                    pool[(lane + 32)*65 + wloc] =
                        ((mdef >> (lane + 32)) & 1ull) ? 1.0f : 0.0f;
                if (lane == 0) {
                    if (mdef)
                        atomicMin(skey,
                            (int)((__ffsll((long long)mdef) - 1)*WP_ + wg));
                    unsigned long long need = mband & ~mdef;
                    if (need) {
                        int nfm = __popcll(need);
                        int base = atomicAdd(&g_nfix, nfm);
                        unsigned long long m = need;
                        while (m) {
                            int fm = __ffsll((long long)m) - 1;
                            m &= m - 1;
                            if (base < CAPFIX)
                                g_fixlist[base] =
                                    (((sec*T_ + t)*64 + fm) << 9) | wg;
                            ++base;
                        }
                    }
                }
            }
        }
    }
    __syncthreads();

    // ---- coalesced pooled store + winner key ----
    for (int i = tid; i < FM_*WIN_BLK; i += 256) {
        int fm = i >> 6, w = i & 63;
        if (wgbase + w < WP_)
            out[((sec*T_ + t)*FM_ + fm)*WP_ + wgbase + w] = pool[fm*65 + w];
    }
    if (tid == 0 && *skey != INT_MAX)
        atomicMin(&g_key[sec], (t << 15) | *skey);
}

// Exact recompute of band windows in the reference-matching fp32 chain order
// (kh outer ascending, kw inner ascending, single fmaf chain per cell).
// NOTE: loops left unrollable — unrolling preserves the serial fmaf chain
// order while letting the compiler pipeline the independent loads.
__global__ void fixup_kernel(const float* __restrict__ x,
                             const float* __restrict__ W,
                             float* __restrict__ out) {
    int n = g_nfix;
    if (n > CAPFIX) n = CAPFIX;
    int lane = threadIdx.x & 31;
    int warp = (blockIdx.x*blockDim.x + threadIdx.x) >> 5;
    int nwarp = (gridDim.x*blockDim.x) >> 5;
    for (int e = warp; e < n; e += nwarp) {
        int rec = g_fixlist[e];
        int wg = rec & 511;
        int sf = rec >> 9;
        int fm = sf & 63;
        int st = sf >> 6;
        int sec = st / T_, t = st - sec*T_;
        bool fire = false;
        if (lane < 16) {
            int oh = lane >> 2;
            int ow = wg*4 + (lane & 3);
            const float* xg = x + (t*H_ + 4*sec)*WD_;
            const float* wv = W + (sec*FM_ + fm)*240;
            float acc = 0.0f;
#pragma unroll
            for (int kh = 0; kh < KH_; ++kh) {
                const float* xr = xg + (oh + kh)*WD_ + ow;
                const float* wr = wv + kh*KW_;
#pragma unroll 8
                for (int kw = 0; kw < KW_; ++kw)
                    acc = fmaf(xr[kw], wr[kw], acc);
            }
            fire = acc > THRESHF;
        }
        unsigned bal = __ballot_sync(0xffffffffu, fire);
        if (bal && lane == 0) {
            out[((sec*T_ + t)*FM_ + fm)*WP_ + wg] = 1.0f;
            atomicMin(&g_key[sec], (t << 15) | (fm*WP_ + wg));
        }
    }
}

__global__ void finalize_kernel(float* __restrict__ out, long long out_size) {
    int s = threadIdx.x;
    if (s < NSEC && out_size >= (long long)(POOLED_ELEMS + NSEC)) {
        int k = g_key[s];
        out[POOLED_ELEMS + s] = (k == INT_MAX) ? -1.0f
                                               : (float)((k & 32767) / WP_);
    }
}

extern "C" void kernel_launch(void* const* d_in, const int* in_sizes, int n_in,
                              void* d_out, int out_size) {
    const float* x = (const float*)d_in[0];
    const float* W = (const float*)d_in[1];
    if (n_in >= 2 && in_sizes[0] == NSEC*FM_*KH_*KW_) {
        const float* tmp = x; x = W; W = tmp;
    }
    float* out = (float*)d_out;

    cudaFuncSetAttribute(conv_mma_kernel,
                         cudaFuncAttributeMaxDynamicSharedMemorySize, SM_TOTAL);

    init_keys_kernel<<<1, 32>>>();
    prep_bfrag_kernel<<<NSEC, 256>>>(W);
    conv_mma_kernel<<<NSEC*T_*8, 256, SM_TOTAL>>>(x, out);
    fixup_kernel<<<1024, 128>>>(x, W, out);
    finalize_kernel<<<1, 32>>>(out, (long long)out_size);
}